// round 16
// baseline (speedup 1.0000x reference)
#include <cuda_runtime.h>
#include <math.h>

#define NN 128
#define DIMC 64
#define DI 512
#define HEADS 8
#define DHEAD 64
#define SSC 5
#define DMLP 1024
#define SDI 2560
#define LN_EPS 1e-5f

typedef unsigned long long u64;

__device__ __forceinline__ u64 dup2(float v){ u64 r; asm("mov.b64 %0, {%1, %1};" : "=l"(r) : "f"(v)); return r; }
__device__ __forceinline__ u64 fma2(u64 a, u64 b, u64 c){ u64 d; asm("fma.rn.f32x2 %0, %1, %2, %3;" : "=l"(d) : "l"(a), "l"(b), "l"(c)); return d; }
__device__ __forceinline__ u64 add2(u64 a, u64 b){ u64 d; asm("add.rn.f32x2 %0, %1, %2;" : "=l"(d) : "l"(a), "l"(b)); return d; }
__device__ __forceinline__ float2 unpk(u64 v){ float2 f; asm("mov.b64 {%0, %1}, %2;" : "=f"(f.x), "=f"(f.y) : "l"(v)); return f; }

__device__ __align__(16) float g_hi[NN*DIMC];
__device__ __align__(16) float g_hj[NN*DIMC];
__device__ __align__(16) float g_q[NN*DI];
__device__ __align__(16) float g_k[NN*DI];
__device__ __align__(16) float g_actv[NN*DMLP];
__device__ __align__(16) float g_actp[NN*DMLP];
__device__ __align__(16) float g_v[NN*SDI];
__device__ __align__(16) float g_pav[NN*SDI];
__device__ __align__(16) float g_evsum[NN*SDI];
__device__ __align__(16) float g_sn[HEADS*NN*NN];
__device__ __align__(16) float g_den[HEADS*NN*SSC];
__device__ __align__(16) float g_vc[NN*SSC*HEADS*DIMC];
__device__ __align__(16) float g_G[NN*SSC*DIMC*DIMC];
__device__ __align__(16) float g_out[NN*NN*SSC*DIMC];

// ---------- LN: 64 thr/row, per-warp butterfly tree, two-warp combine, rsqrtf ----------
__global__ void k_ln(const float* __restrict__ h,
                     const float* __restrict__ wi, const float* __restrict__ wj){
    int i = blockIdx.x, c = threadIdx.x;  // 64 threads
    __shared__ float sb[2];
    float x = h[i*DIMC + c];
    float s = x;
    #pragma unroll
    for (int o=16;o>0;o>>=1) s += __shfl_xor_sync(0xffffffffu, s, o);
    if ((c&31)==0) sb[c>>5] = s;
    __syncthreads();
    float mean = (sb[0]+sb[1]) * (1.0f/64.0f);
    float d = x - mean;
    float vs = d*d;
    #pragma unroll
    for (int o=16;o>0;o>>=1) vs += __shfl_xor_sync(0xffffffffu, vs, o);
    __syncthreads();
    if ((c&31)==0) sb[c>>5] = vs;
    __syncthreads();
    float rstd = rsqrtf((sb[0]+sb[1])*(1.0f/64.0f) + LN_EPS);
    g_hi[i*DIMC+c] = d*rstd*wi[c];
    g_hj[i*DIMC+c] = d*rstd*wj[c];
}

// ---------- q (fp32, c-sequential FMA like cublas K=64) ----------
__global__ __launch_bounds__(256) void k_q(const float* __restrict__ Wq){
    int i = blockIdx.x, tid = threadIdx.x;
    __shared__ float his[DIMC];
    if (tid < 64) his[tid] = g_hi[i*DIMC + tid];
    __syncthreads();
    #pragma unroll
    for (int k=0;k<2;k++){
        int u = tid + k*256;
        float acc = 0.f;
        #pragma unroll
        for (int c=0;c<64;c++) acc = fmaf(his[c], Wq[c*DI+u], acc);
        g_q[i*DI+u] = acc;
    }
}

// ---------- evsum (R13 best): j-pair packing (k,k+16), kc-chunk 8, one i per block ----------
__global__ __launch_bounds__(128) void k_evsum(const float* __restrict__ We,
                                               const float* __restrict__ t){
    extern __shared__ float2 tsd[];   // [tb 4][k 16][c 64]: (t[i,32tb+k,c], t[i,32tb+16+k,c]) 32KB
    int i = blockIdx.y, tid = threadIdx.x;
    int n = blockIdx.x*128 + tid;
    const float* tb0 = t + i*NN*DIMC;
    #pragma unroll
    for (int it=0; it<32; it++){
        int idx = it*128 + tid;
        int tb = idx>>10, k = (idx>>6)&15, c = idx&63;
        tsd[idx] = make_float2(tb0[(tb*32+k)*DIMC + c], tb0[(tb*32+16+k)*DIMC + c]);
    }
    float w[64];
    #pragma unroll
    for (int c=0;c<64;c++) w[c] = We[c*SDI + n];
    __syncthreads();
    u64 p2[16];
    #pragma unroll
    for (int k=0;k<16;k++) p2[k]=0ull;
    #pragma unroll
    for (int tb=0; tb<4; tb++){
        #pragma unroll
        for (int kc=0; kc<16; kc+=8){
            u64 e2[8];
            #pragma unroll
            for (int k=0;k<8;k++) e2[k]=0ull;
            const float2* base = tsd + (tb*16 + kc)*64;
            for (int c=0;c<64;c+=2){
                u64 w0 = dup2(w[c]), w1 = dup2(w[c+1]);
                #pragma unroll
                for (int k=0;k<8;k++){
                    ulonglong2 tt = *(const ulonglong2*)(base + k*64 + c);
                    e2[k] = fma2(tt.x, w0, e2[k]);
                    e2[k] = fma2(tt.y, w1, e2[k]);
                }
            }
            #pragma unroll
            for (int k=0;k<8;k++) p2[kc+k] = add2(p2[kc+k], e2[k]);
        }
    }
    float s[16];
    #pragma unroll
    for (int k=0;k<16;k++){ float2 v = unpk(p2[k]); s[k] = __fadd_rn(v.x, v.y); }
    #pragma unroll
    for (int off=8; off>0; off>>=1){
        #pragma unroll
        for (int k=0;k<off;k++) s[k] = __fadd_rn(s[k], s[k+off]);
    }
    g_evsum[i*SDI + n] = s[0];
}

// ---------- den[h,i,s]: two-half-tree row reduce ----------
__global__ __launch_bounds__(256) void k_den(){
    int i = blockIdx.x, s = blockIdx.y;
    int lane = threadIdx.x & 31, h = threadIdx.x >> 5;
    const float* qp = &g_q[i*DI + h*DHEAD];
    const float* ep = &g_evsum[i*SDI + s*DI + h*DHEAD];
    float plo = __fmul_rn(qp[lane],      ep[lane]);
    float phi = __fmul_rn(qp[lane + 32], ep[lane + 32]);
    #pragma unroll
    for (int off=16; off>0; off>>=1){
        plo = __fadd_rn(plo, __shfl_down_sync(0xffffffffu, plo, off));
        phi = __fadd_rn(phi, __shfl_down_sync(0xffffffffu, phi, off));
    }
    if (lane == 0) g_den[(h*NN+i)*SSC + s] = __fadd_rn(plo, phi);
}

// ---------- small GEMMs: (128x64) @ (64xNcols) ----------
__global__ __launch_bounds__(256) void k_gemm_k64(int which, const float* __restrict__ W,
                           const float* __restrict__ bias, int Ncols, int doSilu){
    const float* A = g_hj; float* C;
    switch (which){
        case 1: C=g_k;    break;
        case 2: C=g_actv; break;
        default:C=g_actp; break;
    }
    __shared__ float As[32][64];
    int r0 = blockIdx.y*32, c0 = blockIdx.x*64;
    int tid = threadIdx.x;
    #pragma unroll
    for (int it=0; it<2; it++){
        int lin = tid + it*256;
        int rr = lin>>4, qq = lin&15;
        *(float4*)&As[rr][qq*4] = *(const float4*)&A[(r0+rr)*DIMC + qq*4];
    }
    __syncthreads();
    int col = tid&63, rg = tid>>6;
    float acc[8];
    #pragma unroll
    for (int r=0;r<8;r++) acc[r]=0.f;
    for (int kk=0;kk<64;kk++){
        float w = W[kk*Ncols + c0 + col];
        #pragma unroll
        for (int r=0;r<8;r++) acc[r] += As[rg+4*r][kk]*w;
    }
    float bv = bias ? bias[c0+col] : 0.f;
    #pragma unroll
    for (int r=0;r<8;r++){
        float v = acc[r] + bv;
        if (doSilu) v = v / (1.0f + expf(-v));
        C[(r0+rg+4*r)*Ncols + c0 + col] = v;
    }
}

// ---------- v/pav: (128x1024)@(1024x2560)+b — split per matrix (which: 0=v, 1=pav) ----------
__global__ __launch_bounds__(128) void k_mlp2(int which,
                       const float* __restrict__ Wv2, const float* __restrict__ bv2,
                       const float* __restrict__ Wp2, const float* __restrict__ bp2){
    const float* A    = which ? g_actp : g_actv;
    const float* W    = which ? Wp2    : Wv2;
    const float* bias = which ? bp2    : bv2;
    float*       C    = which ? g_pav  : g_v;
    __shared__ float As[32][68];
    __shared__ float Bs[32][64];
    int r0 = blockIdx.y*64, c0 = blockIdx.x*64;
    int tid = threadIdx.x;
    int ty = tid>>3, tx = tid&7;
    u64 acc[4][4];
    #pragma unroll
    for (int r=0;r<4;r++){ acc[r][0]=0ull; acc[r][1]=0ull; acc[r][2]=0ull; acc[r][3]=0ull; }
    for (int k0=0;k0<DMLP;k0+=32){
        __syncthreads();
        #pragma unroll
        for (int it=0;it<4;it++){
            int lin = tid + it*128;
            int row = lin>>3, kq = lin&7;
            float4 a = *(const float4*)&A[(r0+row)*DMLP + k0 + kq*4];
            As[kq*4+0][row]=a.x; As[kq*4+1][row]=a.y; As[kq*4+2][row]=a.z; As[kq*4+3][row]=a.w;
        }
        #pragma unroll
        for (int it=0;it<4;it++){
            int lin = tid + it*128;
            int kr = lin>>4, mq = lin&15;
            *(float4*)&Bs[kr][mq*4] = *(const float4*)&W[(k0+kr)*SDI + c0 + mq*4];
        }
        __syncthreads();
        #pragma unroll
        for (int kk=0;kk<32;kk++){
            float4 a4 = *(const float4*)&As[kk][ty*4];
            u64 b0 = *(const u64*)&Bs[kk][tx*8+0];
            u64 b1 = *(const u64*)&Bs[kk][tx*8+2];
            u64 b2 = *(const u64*)&Bs[kk][tx*8+4];
            u64 b3 = *(const u64*)&Bs[kk][tx*8+6];
            u64 a0=dup2(a4.x), a1=dup2(a4.y), a2=dup2(a4.z), a3=dup2(a4.w);
            acc[0][0]=fma2(a0,b0,acc[0][0]); acc[0][1]=fma2(a0,b1,acc[0][1]); acc[0][2]=fma2(a0,b2,acc[0][2]); acc[0][3]=fma2(a0,b3,acc[0][3]);
            acc[1][0]=fma2(a1,b0,acc[1][0]); acc[1][1]=fma2(a1,b1,acc[1][1]); acc[1][2]=fma2(a1,b2,acc[1][2]); acc[1][3]=fma2(a1,b3,acc[1][3]);
            acc[2][0]=fma2(a2,b0,acc[2][0]); acc[2][1]=fma2(a2,b1,acc[2][1]); acc[2][2]=fma2(a2,b2,acc[2][2]); acc[2][3]=fma2(a2,b3,acc[2][3]);
            acc[3][0]=fma2(a3,b0,acc[3][0]); acc[3][1]=fma2(a3,b1,acc[3][1]); acc[3][2]=fma2(a3,b2,acc[3][2]); acc[3][3]=fma2(a3,b3,acc[3][3]);
        }
    }
    #pragma unroll
    for (int r=0;r<4;r++){
        int row = r0 + ty*4 + r;
        float2 p0=unpk(acc[r][0]), p1=unpk(acc[r][1]), p2=unpk(acc[r][2]), p3=unpk(acc[r][3]);
        int cb = c0 + tx*8;
        float4 o1 = {p0.x+bias[cb+0], p0.y+bias[cb+1], p1.x+bias[cb+2], p1.y+bias[cb+3]};
        float4 o2 = {p2.x+bias[cb+4], p2.y+bias[cb+5], p3.x+bias[cb+6], p3.y+bias[cb+7]};
        *(float4*)&C[row*SDI + cb]     = o1;
        *(float4*)&C[row*SDI + cb + 4] = o2;
    }
}

// ---------- sim_num[h,i,j] ----------
__global__ __launch_bounds__(256) void k_sn(){
    __shared__ float qs[16][68], ks[16][68];
    int h = blockIdx.z, i0 = blockIdx.y*16, j0 = blockIdx.x*16;
    int tid = threadIdx.x;
    { int rr = tid>>4, qq = tid&15;
      *(float4*)&qs[rr][qq*4] = *(const float4*)&g_q[(i0+rr)*DI + h*DHEAD + qq*4];
      *(float4*)&ks[rr][qq*4] = *(const float4*)&g_k[(j0+rr)*DI + h*DHEAD + qq*4]; }
    __syncthreads();
    int ty = tid>>4, tx = tid&15;
    float acc = 0.f;
    #pragma unroll
    for (int d=0;d<DHEAD;d++) acc = fmaf(qs[ty][d], ks[tx][d], acc);
    g_sn[(h*NN + i0+ty)*NN + j0+tx] = acc;
}

// ---------- vc[j,s,h,m] ----------
__global__ __launch_bounds__(256) void k_vc(const float* __restrict__ Wc){
    int j = blockIdx.x, s = blockIdx.y;
    __shared__ float vs[DI];
    int tid = threadIdx.x;
    vs[tid]     = g_v[j*SDI + s*DI + tid];
    vs[tid+256] = g_v[j*SDI + s*DI + 256 + tid];
    __syncthreads();
    int m = tid&63, h0 = tid>>6;
    #pragma unroll
    for (int hh=0; hh<2; hh++){
        int h = h0 + hh*4;
        float acc = 0.f;
        #pragma unroll
        for (int d=0;d<DHEAD;d++) acc = fmaf(vs[h*DHEAD+d], Wc[(h*DHEAD+d)*DIMC + m], acc);
        g_vc[((j*SSC+s)*HEADS + h)*DIMC + m] = acc;
    }
}

// ---------- G v2: 2-j tiling, pre-duplicated Ws2 pairs, 256 thr ----------
// G[j,s,c,m] = sum_u We[c,su]*pav[j,su]*Wc[u,m]; same per-element chain as v1 (bit-exact).
__global__ __launch_bounds__(256) void k_G(const float* __restrict__ We, const float* __restrict__ Wc){
    int jp = blockIdx.x, s = blockIdx.y;
    __shared__ float2 ps2[DI];           // (pav[j0,u], pav[j1,u]) 4KB
    __shared__ float2 Ws2[2][32][64];    // [j][u][c] dup pairs (v,v) 32KB
    __shared__ float Wcs[32][68];        // 8.5KB
    int tid = threadIdx.x;
    int j0 = 2*jp, j1 = 2*jp+1;
    #pragma unroll
    for (int it=0; it<2; it++){
        int u = it*256 + tid;
        ps2[u] = make_float2(g_pav[j0*SDI + s*DI + u], g_pav[j1*SDI + s*DI + u]);
    }
    int tyc = tid>>4, tx = tid&15;       // c = tyc*4..+3, m = tx*4..+3
    u64 acc[2][4][2];
    #pragma unroll
    for (int jj=0;jj<2;jj++)
        #pragma unroll
        for (int r=0;r<4;r++){ acc[jj][r][0]=0ull; acc[jj][r][1]=0ull; }
    for (int k0=0;k0<DI;k0+=32){
        __syncthreads();
        #pragma unroll
        for (int it=0;it<2;it++){
            int lin = tid + it*256;      // 512: c 64 x uq 8
            int c = lin>>3, uq = lin&7;
            float4 w = *(const float4*)&We[c*SDI + s*DI + k0 + uq*4];
            float2 p0 = ps2[k0+uq*4+0], p1 = ps2[k0+uq*4+1];
            float2 p2 = ps2[k0+uq*4+2], p3 = ps2[k0+uq*4+3];
            Ws2[0][uq*4+0][c] = make_float2(w.x*p0.x, w.x*p0.x);
            Ws2[1][uq*4+0][c] = make_float2(w.x*p0.y, w.x*p0.y);
            Ws2[0][uq*4+1][c] = make_float2(w.y*p1.x, w.y*p1.x);
            Ws2[1][uq*4+1][c] = make_float2(w.y*p1.y, w.y*p1.y);
            Ws2[0][uq*4+2][c] = make_float2(w.z*p2.x, w.z*p2.x);
            Ws2[1][uq*4+2][c] = make_float2(w.z*p2.y, w.z*p2.y);
            Ws2[0][uq*4+3][c] = make_float2(w.w*p3.x, w.w*p3.x);
            Ws2[1][uq*4+3][c] = make_float2(w.w*p3.y, w.w*p3.y);
        }
        #pragma unroll
        for (int it=0;it<2;it++){
            int lin = tid + it*256;      // 512: kr 32 x mq 16
            int kr = lin>>4, mq = lin&15;
            *(float4*)&Wcs[kr][mq*4] = *(const float4*)&Wc[(k0+kr)*DIMC + mq*4];
        }
        __syncthreads();
        #pragma unroll
        for (int kk=0;kk<32;kk++){
            u64 b0 = *(const u64*)&Wcs[kk][tx*4];
            u64 b1 = *(const u64*)&Wcs[kk][tx*4+2];
            ulonglong2 a0lo = *(const ulonglong2*)&Ws2[0][kk][tyc*4];
            ulonglong2 a0hi = *(const ulonglong2*)&Ws2[0][kk][tyc*4+2];
            ulonglong2 a1lo = *(const ulonglong2*)&Ws2[1][kk][tyc*4];
            ulonglong2 a1hi = *(const ulonglong2*)&Ws2[1][kk][tyc*4+2];
            acc[0][0][0]=fma2(a0lo.x,b0,acc[0][0][0]); acc[0][0][1]=fma2(a0lo.x,b1,acc[0][0][1]);
            acc[0][1][0]=fma2(a0lo.y,b0,acc[0][1][0]); acc[0][1][1]=fma2(a0lo.y,b1,acc[0][1][1]);
            acc[0][2][0]=fma2(a0hi.x,b0,acc[0][2][0]); acc[0][2][1]=fma2(a0hi.x,b1,acc[0][2][1]);
            acc[0][3][0]=fma2(a0hi.y,b0,acc[0][3][0]); acc[0][3][1]=fma2(a0hi.y,b1,acc[0][3][1]);
            acc[1][0][0]=fma2(a1lo.x,b0,acc[1][0][0]); acc[1][0][1]=fma2(a1lo.x,b1,acc[1][0][1]);
            acc[1][1][0]=fma2(a1lo.y,b0,acc[1][1][0]); acc[1][1][1]=fma2(a1lo.y,b1,acc[1][1][1]);
            acc[1][2][0]=fma2(a1hi.x,b0,acc[1][2][0]); acc[1][2][1]=fma2(a1hi.x,b1,acc[1][2][1]);
            acc[1][3][0]=fma2(a1hi.y,b0,acc[1][3][0]); acc[1][3][1]=fma2(a1hi.y,b1,acc[1][3][1]);
        }
    }
    #pragma unroll
    for (int jj=0;jj<2;jj++){
        float* Gp = &g_G[((2*jp+jj)*SSC+s)*DIMC*DIMC];
        #pragma unroll
        for (int r=0;r<4;r++){
            int c = tyc*4 + r;
            float2 v0 = unpk(acc[jj][r][0]), v1 = unpk(acc[jj][r][1]);
            float4 o = {v0.x, v0.y, v1.x, v1.y};
            *(float4*)&Gp[c*DIMC + tx*4] = o;
        }
    }
}

// ---------- out[i,j,s,m]: 16 i x 4 j per block ----------
__global__ __launch_bounds__(256) void k_out(const float* __restrict__ t){
    int i0 = blockIdx.y*16, j0 = blockIdx.x*4;
    __shared__ float tst[4][68][16];
    __shared__ float Gs[4*1032];
    __shared__ float vcs[4][8][64];
    __shared__ float sns[8][16][4];
    __shared__ float dens[8][16][5];
    int tid = threadIdx.x;
    #pragma unroll
    for (int it=0; it<4; it++){
        int lin = tid + it*256;
        int il = lin&15, jl2 = (lin>>4)&3, cq = lin>>6;
        float4 v = *(const float4*)&t[((i0+il)*NN + j0+jl2)*DIMC + cq*4];
        tst[jl2][cq*4+0][il]=v.x; tst[jl2][cq*4+1][il]=v.y; tst[jl2][cq*4+2][il]=v.z; tst[jl2][cq*4+3][il]=v.w;
    }
    if (tid < 128){
        int h = tid>>4, il = tid&15;
        *(float4*)&sns[h][il][0] = *(const float4*)&g_sn[(h*NN + i0+il)*NN + j0];
    }
    for (int lin = tid; lin < 640; lin += 256){
        int h = lin/80, rem = lin%80;
        dens[h][rem/5][rem%5] = g_den[(h*NN + i0 + rem/5)*SSC + rem%5];
    }
    int jl = tid>>6, r2 = tid&63;
    int tr = r2>>4, tc = r2&15;
    __syncthreads();
    for (int s=0; s<SSC; s++){
        __syncthreads();
        #pragma unroll
        for (int it=0; it<2; it++){
            int lin = tid + it*256;
            int jj = lin>>7, rem = lin&127;
            int h = rem>>4, mq = rem&15;
            *(float4*)&vcs[jj][h][mq*4] = *(const float4*)&g_vc[(((j0+jj)*SSC+s)*HEADS + h)*DIMC + mq*4];
        }
        __syncthreads();
        u64 acc[4][2];
        #pragma unroll
        for (int r=0;r<4;r++){ acc[r][0]=0ull; acc[r][1]=0ull; }
        #pragma unroll
        for (int h=0; h<HEADS; h++){
            u64 b0 = *(const u64*)&vcs[jl][h][tc*4];
            u64 b1 = *(const u64*)&vcs[jl][h][tc*4+2];
            #pragma unroll
            for (int r=0;r<4;r++){
                int il = tr*4 + r;
                float av = __fdiv_rn(sns[h][il][jl], dens[h][il][s]);
                u64 a = dup2(av);
                acc[r][0]=fma2(a,b0,acc[r][0]); acc[r][1]=fma2(a,b1,acc[r][1]);
            }
        }
        for (int ch=0; ch<4; ch++){
            __syncthreads();
            #pragma unroll
            for (int it=0; it<4; it++){
                int lin = tid + it*256;
                int jj = lin>>8, rem = lin&255;
                int cc = rem>>4, mq = rem&15;
                *(float4*)&Gs[jj*1032 + cc*64 + mq*4] =
                    *(const float4*)&g_G[(((j0+jj)*SSC+s)*DIMC + ch*16+cc)*DIMC + mq*4];
            }
            __syncthreads();
            #pragma unroll
            for (int cc=0; cc<16; cc++){
                u64 b0 = *(const u64*)&Gs[jl*1032 + cc*64 + tc*4];
                u64 b1 = *(const u64*)&Gs[jl*1032 + cc*64 + tc*4+2];
                float4 a4 = *(const float4*)&tst[jl][ch*16+cc][tr*4];
                u64 a0=dup2(a4.x), a1=dup2(a4.y), a2=dup2(a4.z), a3=dup2(a4.w);
                acc[0][0]=fma2(a0,b0,acc[0][0]); acc[0][1]=fma2(a0,b1,acc[0][1]);
                acc[1][0]=fma2(a1,b0,acc[1][0]); acc[1][1]=fma2(a1,b1,acc[1][1]);
                acc[2][0]=fma2(a2,b0,acc[2][0]); acc[2][1]=fma2(a2,b1,acc[2][1]);
                acc[3][0]=fma2(a3,b0,acc[3][0]); acc[3][1]=fma2(a3,b1,acc[3][1]);
            }
        }
        #pragma unroll
        for (int r=0;r<4;r++){
            float2 v0 = unpk(acc[r][0]), v1 = unpk(acc[r][1]);
            float4 o = {v0.x, v0.y, v1.x, v1.y};
            int il = tr*4 + r;
            *(float4*)&g_out[(((i0+il)*NN + j0+jl)*SSC + s)*DIMC + tc*4] = o;
        }
    }
}

// ---------- epilogues: 256-thread, 4 j-chunks + smem combine ----------
__global__ __launch_bounds__(256) void k_hres(const float* __restrict__ h, float* __restrict__ out){
    int i = blockIdx.x;
    int m = threadIdx.x & 63, jc = threadIdx.x >> 6;
    __shared__ float sp[4][64];
    float acc = 0.f;
    const float* p = &g_out[(i*NN + jc*32)*SSC*DIMC + m];
    #pragma unroll 8
    for (int j=0;j<32;j++) acc += p[j*SSC*DIMC];
    sp[jc][m] = acc;
    __syncthreads();
    if (threadIdx.x < 64)
        out[i*DIMC + threadIdx.x] = h[i*DIMC + threadIdx.x]
            + sp[0][threadIdx.x] + sp[1][threadIdx.x] + sp[2][threadIdx.x] + sp[3][threadIdx.x];
}
__global__ __launch_bounds__(256) void k_x1res(const float* __restrict__ x1, const float* __restrict__ r1,
                        float* __restrict__ out){
    int i = blockIdx.x;
    int d = threadIdx.x & 63, jc = threadIdx.x >> 6;
    __shared__ float sp[4][64][3];
    float a0=0.f, a1=0.f, a2=0.f;
    #pragma unroll 4
    for (int jj=0;jj<32;jj++){
        int j = jc*32 + jj;
        float o3 = g_out[((i*NN+j)*SSC + 3)*DIMC + d];
        float o1 = g_out[((i*NN+j)*SSC + 1)*DIMC + d];
        const float* xp = &x1[(j*DIMC + d)*3];
        const float* rp = &r1[(i*NN + j)*3];
        a0 += xp[0]*o3 + rp[0]*o1;
        a1 += xp[1]*o3 + rp[1]*o1;
        a2 += xp[2]*o3 + rp[2]*o1;
    }
    sp[jc][d][0]=a0; sp[jc][d][1]=a1; sp[jc][d][2]=a2;
    __syncthreads();
    if (threadIdx.x < 64){
        int dd = threadIdx.x;
        #pragma unroll
        for (int m=0;m<3;m++)
            out[(i*DIMC+dd)*3+m] = sp[0][dd][m]+sp[1][dd][m]+sp[2][dd][m]+sp[3][dd][m];
    }
}
__global__ __launch_bounds__(256) void k_x2res(const float* __restrict__ x2, const float* __restrict__ r2,
                        float* __restrict__ out){
    int i = blockIdx.x;
    int d = threadIdx.x & 63, jc = threadIdx.x >> 6;
    __shared__ float sp[4][64][5];
    float a[5] = {0.f,0.f,0.f,0.f,0.f};
    #pragma unroll 4
    for (int jj=0;jj<32;jj++){
        int j = jc*32 + jj;
        float o4 = g_out[((i*NN+j)*SSC + 4)*DIMC + d];
        float o2 = g_out[((i*NN+j)*SSC + 2)*DIMC + d];
        const float* xp = &x2[(j*DIMC + d)*5];
        const float* rp = &r2[(i*NN + j)*5];
        #pragma unroll
        for (int m=0;m<5;m++) a[m] += xp[m]*o4 + rp[m]*o2;
    }
    #pragma unroll
    for (int m=0;m<5;m++) sp[jc][d][m] = a[m];
    __syncthreads();
    if (threadIdx.x < 64){
        int dd = threadIdx.x;
        #pragma unroll
        for (int m=0;m<5;m++)
            out[(i*DIMC+dd)*5+m] = sp[0][dd][m]+sp[1][dd][m]+sp[2][dd][m]+sp[3][dd][m];
    }
}

extern "C" void kernel_launch(void* const* d_in, const int* in_sizes, int n_in,
                              void* d_out, int out_size){
    const float* h    = (const float*)d_in[0];
    const float* x1   = (const float*)d_in[1];
    const float* x2   = (const float*)d_in[2];
    const float* t_ij = (const float*)d_in[3];
    const float* r1   = (const float*)d_in[4];
    const float* r2   = (const float*)d_in[5];
    const float* wi   = (const float*)d_in[6];
    const float* wj   = (const float*)d_in[7];
    const float* Wq   = (const float*)d_in[8];
    const float* Wk   = (const float*)d_in[9];
    const float* Wv1  = (const float*)d_in[10];
    const float* bv1  = (const float*)d_in[11];
    const float* Wv2  = (const float*)d_in[12];
    const float* bv2  = (const float*)d_in[13];
    const float* Wp1  = (const float*)d_in[14];
    const float* bp1  = (const float*)d_in[15];
    const float* Wp2  = (const float*)d_in[16];
    const float* bp2  = (const float*)d_in[17];
    const float* We   = (const float*)d_in[18];
    const float* Wc   = (const float*)d_in[19];
    float* out = (float*)d_out;

    // k_G stays in the 4th slot (the one ncu captures).
    k_ln<<<NN, 64>>>(h, wi, wj);
    k_gemm_k64<<<dim3(16,4), 256>>>(3, Wp1, bp1,     DMLP, 1);   // actp
    k_mlp2<<<dim3(40,2), 128>>>(1, Wv2, bv2, Wp2, bp2);          // pav
    k_G<<<dim3(64,SSC), 256>>>(We, Wc);                          // <- PROFILED
    k_q<<<NN, 256>>>(Wq);
    k_gemm_k64<<<dim3(8,4),  256>>>(1, Wk,  nullptr, DI,   0);   // k
    k_evsum<<<dim3(20, NN), 128, 32768>>>(We, t_ij);
    k_den<<<dim3(NN, SSC), 256>>>();
    k_gemm_k64<<<dim3(16,4), 256>>>(2, Wv1, bv1,     DMLP, 1);   // actv
    k_mlp2<<<dim3(40,2), 128>>>(0, Wv2, bv2, Wp2, bp2);          // v
    k_sn<<<dim3(8,8,8), 256>>>();
    k_vc<<<dim3(NN,SSC), 256>>>(Wc);
    k_out<<<dim3(32,8), 256>>>(t_ij);
    k_hres<<<NN, 256>>>(h, out);
    k_x1res<<<NN, 256>>>(x1, r1, out + NN*DIMC);
    k_x2res<<<NN, 256>>>(x2, r2, out + NN*DIMC*4);
}

// round 17
// speedup vs baseline: 1.1210x; 1.1210x over previous
#include <cuda_runtime.h>
#include <math.h>

#define NN 128
#define DIMC 64
#define DI 512
#define HEADS 8
#define DHEAD 64
#define SSC 5
#define DMLP 1024
#define SDI 2560
#define LN_EPS 1e-5f

typedef unsigned long long u64;

__device__ __forceinline__ u64 dup2(float v){ u64 r; asm("mov.b64 %0, {%1, %1};" : "=l"(r) : "f"(v)); return r; }
__device__ __forceinline__ u64 fma2(u64 a, u64 b, u64 c){ u64 d; asm("fma.rn.f32x2 %0, %1, %2, %3;" : "=l"(d) : "l"(a), "l"(b), "l"(c)); return d; }
__device__ __forceinline__ u64 add2(u64 a, u64 b){ u64 d; asm("add.rn.f32x2 %0, %1, %2;" : "=l"(d) : "l"(a), "l"(b)); return d; }
__device__ __forceinline__ float2 unpk(u64 v){ float2 f; asm("mov.b64 {%0, %1}, %2;" : "=f"(f.x), "=f"(f.y) : "l"(v)); return f; }

__device__ __align__(16) float g_hi[NN*DIMC];
__device__ __align__(16) float g_hj[NN*DIMC];
__device__ __align__(16) float g_q[NN*DI];
__device__ __align__(16) float g_k[NN*DI];
__device__ __align__(16) float g_actv[NN*DMLP];
__device__ __align__(16) float g_actp[NN*DMLP];
__device__ __align__(16) float g_v[NN*SDI];
__device__ __align__(16) float g_pav[NN*SDI];
__device__ __align__(16) float g_evsum[NN*SDI];
__device__ __align__(16) float g_sn[HEADS*NN*NN];
__device__ __align__(16) float g_den[HEADS*NN*SSC];
__device__ __align__(16) float g_vc[NN*SSC*HEADS*DIMC];
__device__ __align__(16) float g_G[NN*SSC*DIMC*DIMC];
__device__ __align__(16) float g_out[NN*NN*SSC*DIMC];

// ---------- LN: 64 thr/row, per-warp butterfly tree, two-warp combine, rsqrtf ----------
__global__ void k_ln(const float* __restrict__ h,
                     const float* __restrict__ wi, const float* __restrict__ wj){
    int i = blockIdx.x, c = threadIdx.x;  // 64 threads
    __shared__ float sb[2];
    float x = h[i*DIMC + c];
    float s = x;
    #pragma unroll
    for (int o=16;o>0;o>>=1) s += __shfl_xor_sync(0xffffffffu, s, o);
    if ((c&31)==0) sb[c>>5] = s;
    __syncthreads();
    float mean = (sb[0]+sb[1]) * (1.0f/64.0f);
    float d = x - mean;
    float vs = d*d;
    #pragma unroll
    for (int o=16;o>0;o>>=1) vs += __shfl_xor_sync(0xffffffffu, vs, o);
    __syncthreads();
    if ((c&31)==0) sb[c>>5] = vs;
    __syncthreads();
    float rstd = rsqrtf((sb[0]+sb[1])*(1.0f/64.0f) + LN_EPS);
    g_hi[i*DIMC+c] = d*rstd*wi[c];
    g_hj[i*DIMC+c] = d*rstd*wj[c];
}

// ---------- q (fp32, c-sequential FMA like cublas K=64) ----------
__global__ __launch_bounds__(256) void k_q(const float* __restrict__ Wq){
    int i = blockIdx.x, tid = threadIdx.x;
    __shared__ float his[DIMC];
    if (tid < 64) his[tid] = g_hi[i*DIMC + tid];
    __syncthreads();
    #pragma unroll
    for (int k=0;k<2;k++){
        int u = tid + k*256;
        float acc = 0.f;
        #pragma unroll
        for (int c=0;c<64;c++) acc = fmaf(his[c], Wq[c*DI+u], acc);
        g_q[i*DI+u] = acc;
    }
}

// ---------- evsum (R13 best): j-pair packing (k,k+16), kc-chunk 8, one i per block ----------
__global__ __launch_bounds__(128) void k_evsum(const float* __restrict__ We,
                                               const float* __restrict__ t){
    extern __shared__ float2 tsd[];   // [tb 4][k 16][c 64]: (t[i,32tb+k,c], t[i,32tb+16+k,c]) 32KB
    int i = blockIdx.y, tid = threadIdx.x;
    int n = blockIdx.x*128 + tid;
    const float* tb0 = t + i*NN*DIMC;
    #pragma unroll
    for (int it=0; it<32; it++){
        int idx = it*128 + tid;
        int tb = idx>>10, k = (idx>>6)&15, c = idx&63;
        tsd[idx] = make_float2(tb0[(tb*32+k)*DIMC + c], tb0[(tb*32+16+k)*DIMC + c]);
    }
    float w[64];
    #pragma unroll
    for (int c=0;c<64;c++) w[c] = We[c*SDI + n];
    __syncthreads();
    u64 p2[16];
    #pragma unroll
    for (int k=0;k<16;k++) p2[k]=0ull;
    #pragma unroll
    for (int tb=0; tb<4; tb++){
        #pragma unroll
        for (int kc=0; kc<16; kc+=8){
            u64 e2[8];
            #pragma unroll
            for (int k=0;k<8;k++) e2[k]=0ull;
            const float2* base = tsd + (tb*16 + kc)*64;
            for (int c=0;c<64;c+=2){
                u64 w0 = dup2(w[c]), w1 = dup2(w[c+1]);
                #pragma unroll
                for (int k=0;k<8;k++){
                    ulonglong2 tt = *(const ulonglong2*)(base + k*64 + c);
                    e2[k] = fma2(tt.x, w0, e2[k]);
                    e2[k] = fma2(tt.y, w1, e2[k]);
                }
            }
            #pragma unroll
            for (int k=0;k<8;k++) p2[kc+k] = add2(p2[kc+k], e2[k]);
        }
    }
    float s[16];
    #pragma unroll
    for (int k=0;k<16;k++){ float2 v = unpk(p2[k]); s[k] = __fadd_rn(v.x, v.y); }
    #pragma unroll
    for (int off=8; off>0; off>>=1){
        #pragma unroll
        for (int k=0;k<off;k++) s[k] = __fadd_rn(s[k], s[k+off]);
    }
    g_evsum[i*SDI + n] = s[0];
}

// ---------- den[h,i,s]: two-half-tree row reduce ----------
__global__ __launch_bounds__(256) void k_den(){
    int i = blockIdx.x, s = blockIdx.y;
    int lane = threadIdx.x & 31, h = threadIdx.x >> 5;
    const float* qp = &g_q[i*DI + h*DHEAD];
    const float* ep = &g_evsum[i*SDI + s*DI + h*DHEAD];
    float plo = __fmul_rn(qp[lane],      ep[lane]);
    float phi = __fmul_rn(qp[lane + 32], ep[lane + 32]);
    #pragma unroll
    for (int off=16; off>0; off>>=1){
        plo = __fadd_rn(plo, __shfl_down_sync(0xffffffffu, plo, off));
        phi = __fadd_rn(phi, __shfl_down_sync(0xffffffffu, phi, off));
    }
    if (lane == 0) g_den[(h*NN+i)*SSC + s] = __fadd_rn(plo, phi);
}

// ---------- small GEMMs: (128x64) @ (64xNcols) ----------
__global__ __launch_bounds__(256) void k_gemm_k64(int which, const float* __restrict__ W,
                           const float* __restrict__ bias, int Ncols, int doSilu){
    const float* A = g_hj; float* C;
    switch (which){
        case 1: C=g_k;    break;
        case 2: C=g_actv; break;
        default:C=g_actp; break;
    }
    __shared__ float As[32][64];
    int r0 = blockIdx.y*32, c0 = blockIdx.x*64;
    int tid = threadIdx.x;
    #pragma unroll
    for (int it=0; it<2; it++){
        int lin = tid + it*256;
        int rr = lin>>4, qq = lin&15;
        *(float4*)&As[rr][qq*4] = *(const float4*)&A[(r0+rr)*DIMC + qq*4];
    }
    __syncthreads();
    int col = tid&63, rg = tid>>6;
    float acc[8];
    #pragma unroll
    for (int r=0;r<8;r++) acc[r]=0.f;
    for (int kk=0;kk<64;kk++){
        float w = W[kk*Ncols + c0 + col];
        #pragma unroll
        for (int r=0;r<8;r++) acc[r] += As[rg+4*r][kk]*w;
    }
    float bv = bias ? bias[c0+col] : 0.f;
    #pragma unroll
    for (int r=0;r<8;r++){
        float v = acc[r] + bv;
        if (doSilu) v = v / (1.0f + expf(-v));
        C[(r0+rg+4*r)*Ncols + c0 + col] = v;
    }
}

// ---------- v/pav: (128x1024)@(1024x2560)+b (merged, blockIdx.z) ----------
__global__ __launch_bounds__(128) void k_mlp2(const float* __restrict__ Wv2, const float* __restrict__ bv2,
                       const float* __restrict__ Wp2, const float* __restrict__ bp2){
    const float* A    = blockIdx.z ? g_actp : g_actv;
    const float* W    = blockIdx.z ? Wp2    : Wv2;
    const float* bias = blockIdx.z ? bp2    : bv2;
    float*       C    = blockIdx.z ? g_pav  : g_v;
    __shared__ float As[32][68];
    __shared__ float Bs[32][64];
    int r0 = blockIdx.y*64, c0 = blockIdx.x*64;
    int tid = threadIdx.x;
    int ty = tid>>3, tx = tid&7;
    u64 acc[4][4];
    #pragma unroll
    for (int r=0;r<4;r++){ acc[r][0]=0ull; acc[r][1]=0ull; acc[r][2]=0ull; acc[r][3]=0ull; }
    for (int k0=0;k0<DMLP;k0+=32){
        __syncthreads();
        #pragma unroll
        for (int it=0;it<4;it++){
            int lin = tid + it*128;
            int row = lin>>3, kq = lin&7;
            float4 a = *(const float4*)&A[(r0+row)*DMLP + k0 + kq*4];
            As[kq*4+0][row]=a.x; As[kq*4+1][row]=a.y; As[kq*4+2][row]=a.z; As[kq*4+3][row]=a.w;
        }
        #pragma unroll
        for (int it=0;it<4;it++){
            int lin = tid + it*128;
            int kr = lin>>4, mq = lin&15;
            *(float4*)&Bs[kr][mq*4] = *(const float4*)&W[(k0+kr)*SDI + c0 + mq*4];
        }
        __syncthreads();
        #pragma unroll
        for (int kk=0;kk<32;kk++){
            float4 a4 = *(const float4*)&As[kk][ty*4];
            u64 b0 = *(const u64*)&Bs[kk][tx*8+0];
            u64 b1 = *(const u64*)&Bs[kk][tx*8+2];
            u64 b2 = *(const u64*)&Bs[kk][tx*8+4];
            u64 b3 = *(const u64*)&Bs[kk][tx*8+6];
            u64 a0=dup2(a4.x), a1=dup2(a4.y), a2=dup2(a4.z), a3=dup2(a4.w);
            acc[0][0]=fma2(a0,b0,acc[0][0]); acc[0][1]=fma2(a0,b1,acc[0][1]); acc[0][2]=fma2(a0,b2,acc[0][2]); acc[0][3]=fma2(a0,b3,acc[0][3]);
            acc[1][0]=fma2(a1,b0,acc[1][0]); acc[1][1]=fma2(a1,b1,acc[1][1]); acc[1][2]=fma2(a1,b2,acc[1][2]); acc[1][3]=fma2(a1,b3,acc[1][3]);
            acc[2][0]=fma2(a2,b0,acc[2][0]); acc[2][1]=fma2(a2,b1,acc[2][1]); acc[2][2]=fma2(a2,b2,acc[2][2]); acc[2][3]=fma2(a2,b3,acc[2][3]);
            acc[3][0]=fma2(a3,b0,acc[3][0]); acc[3][1]=fma2(a3,b1,acc[3][1]); acc[3][2]=fma2(a3,b2,acc[3][2]); acc[3][3]=fma2(a3,b3,acc[3][3]);
        }
    }
    #pragma unroll
    for (int r=0;r<4;r++){
        int row = r0 + ty*4 + r;
        float2 p0=unpk(acc[r][0]), p1=unpk(acc[r][1]), p2=unpk(acc[r][2]), p3=unpk(acc[r][3]);
        int cb = c0 + tx*8;
        float4 o1 = {p0.x+bias[cb+0], p0.y+bias[cb+1], p1.x+bias[cb+2], p1.y+bias[cb+3]};
        float4 o2 = {p2.x+bias[cb+4], p2.y+bias[cb+5], p3.x+bias[cb+6], p3.y+bias[cb+7]};
        *(float4*)&C[row*SDI + cb]     = o1;
        *(float4*)&C[row*SDI + cb + 4] = o2;
    }
}

// ---------- sim_num[h,i,j] ----------
__global__ __launch_bounds__(256) void k_sn(){
    __shared__ float qs[16][68], ks[16][68];
    int h = blockIdx.z, i0 = blockIdx.y*16, j0 = blockIdx.x*16;
    int tid = threadIdx.x;
    { int rr = tid>>4, qq = tid&15;
      *(float4*)&qs[rr][qq*4] = *(const float4*)&g_q[(i0+rr)*DI + h*DHEAD + qq*4];
      *(float4*)&ks[rr][qq*4] = *(const float4*)&g_k[(j0+rr)*DI + h*DHEAD + qq*4]; }
    __syncthreads();
    int ty = tid>>4, tx = tid&15;
    float acc = 0.f;
    #pragma unroll
    for (int d=0;d<DHEAD;d++) acc = fmaf(qs[ty][d], ks[tx][d], acc);
    g_sn[(h*NN + i0+ty)*NN + j0+tx] = acc;
}

// ---------- vc[j,s,h,m] ----------
__global__ __launch_bounds__(256) void k_vc(const float* __restrict__ Wc){
    int j = blockIdx.x, s = blockIdx.y;
    __shared__ float vs[DI];
    int tid = threadIdx.x;
    vs[tid]     = g_v[j*SDI + s*DI + tid];
    vs[tid+256] = g_v[j*SDI + s*DI + 256 + tid];
    __syncthreads();
    int m = tid&63, h0 = tid>>6;
    #pragma unroll
    for (int hh=0; hh<2; hh++){
        int h = h0 + hh*4;
        float acc = 0.f;
        #pragma unroll
        for (int d=0;d<DHEAD;d++) acc = fmaf(vs[h*DHEAD+d], Wc[(h*DHEAD+d)*DIMC + m], acc);
        g_vc[((j*SSC+s)*HEADS + h)*DIMC + m] = acc;
    }
}

// ---------- G v1 + register double-buffered global loads ----------
// G[j,s,c,m] = sum_u We[c,su]*pav[j,su]*Wc[u,m]; compute DAG identical to v1 (bit-exact).
__global__ __launch_bounds__(128) void k_G(const float* __restrict__ We, const float* __restrict__ Wc){
    int j = blockIdx.x, s = blockIdx.y;
    __shared__ float ps[DI];
    __shared__ float Ws[32][68];
    __shared__ float Wcs[32][64];
    int tid = threadIdx.x;
    ps[tid]     = g_pav[j*SDI + s*DI + tid];
    ps[tid+128] = g_pav[j*SDI + s*DI + 128 + tid];
    ps[tid+256] = g_pav[j*SDI + s*DI + 256 + tid];
    ps[tid+384] = g_pav[j*SDI + s*DI + 384 + tid];
    int ty = tid>>3, tx = tid&7;
    u64 acc[4][4];
    #pragma unroll
    for (int r=0;r<4;r++){ acc[r][0]=0ull; acc[r][1]=0ull; acc[r][2]=0ull; acc[r][3]=0ull; }
    // prefetch tile k0=0 into registers
    float4 wea[4], wca[4];
    #pragma unroll
    for (int it=0;it<4;it++){
        int lin = tid + it*128;
        int c = lin>>3, uq = lin&7;
        wea[it] = *(const float4*)&We[c*SDI + s*DI + uq*4];
        int kr = lin>>4, mq = lin&15;
        wca[it] = *(const float4*)&Wc[kr*DIMC + mq*4];
    }
    __syncthreads();   // ps ready
    for (int k0=0;k0<DI;k0+=32){
        // store current tile from registers (scaled We, raw Wc)
        #pragma unroll
        for (int it=0;it<4;it++){
            int lin = tid + it*128;
            int c = lin>>3, uq = lin&7;
            float4 w = wea[it];
            Ws[uq*4+0][c] = w.x*ps[k0+uq*4+0];
            Ws[uq*4+1][c] = w.y*ps[k0+uq*4+1];
            Ws[uq*4+2][c] = w.z*ps[k0+uq*4+2];
            Ws[uq*4+3][c] = w.w*ps[k0+uq*4+3];
            int kr = lin>>4, mq = lin&15;
            *(float4*)&Wcs[kr][mq*4] = wca[it];
        }
        // prefetch next tile while compute runs
        if (k0 + 32 < DI){
            #pragma unroll
            for (int it=0;it<4;it++){
                int lin = tid + it*128;
                int c = lin>>3, uq = lin&7;
                wea[it] = *(const float4*)&We[c*SDI + s*DI + (k0+32) + uq*4];
                int kr = lin>>4, mq = lin&15;
                wca[it] = *(const float4*)&Wc[(k0+32+kr)*DIMC + mq*4];
            }
        }
        __syncthreads();
        #pragma unroll
        for (int kk=0;kk<32;kk++){
            float4 a4 = *(const float4*)&Ws[kk][ty*4];
            u64 b0 = *(const u64*)&Wcs[kk][tx*8+0];
            u64 b1 = *(const u64*)&Wcs[kk][tx*8+2];
            u64 b2 = *(const u64*)&Wcs[kk][tx*8+4];
            u64 b3 = *(const u64*)&Wcs[kk][tx*8+6];
            u64 a0=dup2(a4.x), a1=dup2(a4.y), a2=dup2(a4.z), a3=dup2(a4.w);
            acc[0][0]=fma2(a0,b0,acc[0][0]); acc[0][1]=fma2(a0,b1,acc[0][1]); acc[0][2]=fma2(a0,b2,acc[0][2]); acc[0][3]=fma2(a0,b3,acc[0][3]);
            acc[1][0]=fma2(a1,b0,acc[1][0]); acc[1][1]=fma2(a1,b1,acc[1][1]); acc[1][2]=fma2(a1,b2,acc[1][2]); acc[1][3]=fma2(a1,b3,acc[1][3]);
            acc[2][0]=fma2(a2,b0,acc[2][0]); acc[2][1]=fma2(a2,b1,acc[2][1]); acc[2][2]=fma2(a2,b2,acc[2][2]); acc[2][3]=fma2(a2,b3,acc[2][3]);
            acc[3][0]=fma2(a3,b0,acc[3][0]); acc[3][1]=fma2(a3,b1,acc[3][1]); acc[3][2]=fma2(a3,b2,acc[3][2]); acc[3][3]=fma2(a3,b3,acc[3][3]);
        }
        __syncthreads();
    }
    float* Gp = &g_G[(j*SSC+s)*DIMC*DIMC];
    #pragma unroll
    for (int r=0;r<4;r++){
        int c = ty*4 + r;
        float2 p0=unpk(acc[r][0]), p1=unpk(acc[r][1]), p2=unpk(acc[r][2]), p3=unpk(acc[r][3]);
        float4 o1 = {p0.x,p0.y,p1.x,p1.y};
        float4 o2 = {p2.x,p2.y,p3.x,p3.y};
        *(float4*)&Gp[c*DIMC + tx*8]     = o1;
        *(float4*)&Gp[c*DIMC + tx*8 + 4] = o2;
    }
}

// ---------- out[i,j,s,m]: 16 i x 4 j per block ----------
__global__ __launch_bounds__(256) void k_out(const float* __restrict__ t){
    int i0 = blockIdx.y*16, j0 = blockIdx.x*4;
    __shared__ float tst[4][68][16];
    __shared__ float Gs[4*1032];
    __shared__ float vcs[4][8][64];
    __shared__ float sns[8][16][4];
    __shared__ float dens[8][16][5];
    int tid = threadIdx.x;
    #pragma unroll
    for (int it=0; it<4; it++){
        int lin = tid + it*256;
        int il = lin&15, jl2 = (lin>>4)&3, cq = lin>>6;
        float4 v = *(const float4*)&t[((i0+il)*NN + j0+jl2)*DIMC + cq*4];
        tst[jl2][cq*4+0][il]=v.x; tst[jl2][cq*4+1][il]=v.y; tst[jl2][cq*4+2][il]=v.z; tst[jl2][cq*4+3][il]=v.w;
    }
    if (tid < 128){
        int h = tid>>4, il = tid&15;
        *(float4*)&sns[h][il][0] = *(const float4*)&g_sn[(h*NN + i0+il)*NN + j0];
    }
    for (int lin = tid; lin < 640; lin += 256){
        int h = lin/80, rem = lin%80;
        dens[h][rem/5][rem%5] = g_den[(h*NN + i0 + rem/5)*SSC + rem%5];
    }
    int jl = tid>>6, r2 = tid&63;
    int tr = r2>>4, tc = r2&15;
    __syncthreads();
    for (int s=0; s<SSC; s++){
        __syncthreads();
        #pragma unroll
        for (int it=0; it<2; it++){
            int lin = tid + it*256;
            int jj = lin>>7, rem = lin&127;
            int h = rem>>4, mq = rem&15;
            *(float4*)&vcs[jj][h][mq*4] = *(const float4*)&g_vc[(((j0+jj)*SSC+s)*HEADS + h)*DIMC + mq*4];
        }
        __syncthreads();
        u64 acc[4][2];
        #pragma unroll
        for (int r=0;r<4;r++){ acc[r][0]=0ull; acc[r][1]=0ull; }
        #pragma unroll
        for (int h=0; h<HEADS; h++){
            u64 b0 = *(const u64*)&vcs[jl][h][tc*4];
            u64 b1 = *(const u64*)&vcs[jl][h][tc*4+2];
            #pragma unroll
            for (int r=0;r<4;r++){
                int il = tr*4 + r;
                float av = __fdiv_rn(sns[h][il][jl], dens[h][il][s]);
                u64 a = dup2(av);
                acc[r][0]=fma2(a,b0,acc[r][0]); acc[r][1]=fma2(a,b1,acc[r][1]);
            }
        }
        for (int ch=0; ch<4; ch++){
            __syncthreads();
            #pragma unroll
            for (int it=0; it<4; it++){
                int lin = tid + it*256;
                int jj = lin>>8, rem = lin&255;
                int cc = rem>>4, mq = rem&15;
                *(float4*)&Gs[jj*1032 + cc*64 + mq*4] =
                    *(const float4*)&g_G[(((j0+jj)*SSC+s)*DIMC + ch*16+cc)*DIMC + mq*4];
            }
            __syncthreads();
            #pragma unroll
            for (int cc=0; cc<16; cc++){
                u64 b0 = *(const u64*)&Gs[jl*1032 + cc*64 + tc*4];
                u64 b1 = *(const u64*)&Gs[jl*1032 + cc*64 + tc*4+2];
                float4 a4 = *(const float4*)&tst[jl][ch*16+cc][tr*4];
                u64 a0=dup2(a4.x), a1=dup2(a4.y), a2=dup2(a4.z), a3=dup2(a4.w);
                acc[0][0]=fma2(a0,b0,acc[0][0]); acc[0][1]=fma2(a0,b1,acc[0][1]);
                acc[1][0]=fma2(a1,b0,acc[1][0]); acc[1][1]=fma2(a1,b1,acc[1][1]);
                acc[2][0]=fma2(a2,b0,acc[2][0]); acc[2][1]=fma2(a2,b1,acc[2][1]);
                acc[3][0]=fma2(a3,b0,acc[3][0]); acc[3][1]=fma2(a3,b1,acc[3][1]);
            }
        }
        #pragma unroll
        for (int r=0;r<4;r++){
            float2 v0 = unpk(acc[r][0]), v1 = unpk(acc[r][1]);
            float4 o = {v0.x, v0.y, v1.x, v1.y};
            int il = tr*4 + r;
            *(float4*)&g_out[(((i0+il)*NN + j0+jl)*SSC + s)*DIMC + tc*4] = o;
        }
    }
}

// ---------- epilogues: 256-thread, 4 j-chunks + smem combine ----------
__global__ __launch_bounds__(256) void k_hres(const float* __restrict__ h, float* __restrict__ out){
    int i = blockIdx.x;
    int m = threadIdx.x & 63, jc = threadIdx.x >> 6;
    __shared__ float sp[4][64];
    float acc = 0.f;
    const float* p = &g_out[(i*NN + jc*32)*SSC*DIMC + m];
    #pragma unroll 8
    for (int j=0;j<32;j++) acc += p[j*SSC*DIMC];
    sp[jc][m] = acc;
    __syncthreads();
    if (threadIdx.x < 64)
        out[i*DIMC + threadIdx.x] = h[i*DIMC + threadIdx.x]
            + sp[0][threadIdx.x] + sp[1][threadIdx.x] + sp[2][threadIdx.x] + sp[3][threadIdx.x];
}
__global__ __launch_bounds__(256) void k_x1res(const float* __restrict__ x1, const float* __restrict__ r1,
                        float* __restrict__ out){
    int i = blockIdx.x;
    int d = threadIdx.x & 63, jc = threadIdx.x >> 6;
    __shared__ float sp[4][64][3];
    float a0=0.f, a1=0.f, a2=0.f;
    #pragma unroll 4
    for (int jj=0;jj<32;jj++){
        int j = jc*32 + jj;
        float o3 = g_out[((i*NN+j)*SSC + 3)*DIMC + d];
        float o1 = g_out[((i*NN+j)*SSC + 1)*DIMC + d];
        const float* xp = &x1[(j*DIMC + d)*3];
        const float* rp = &r1[(i*NN + j)*3];
        a0 += xp[0]*o3 + rp[0]*o1;
        a1 += xp[1]*o3 + rp[1]*o1;
        a2 += xp[2]*o3 + rp[2]*o1;
    }
    sp[jc][d][0]=a0; sp[jc][d][1]=a1; sp[jc][d][2]=a2;
    __syncthreads();
    if (threadIdx.x < 64){
        int dd = threadIdx.x;
        #pragma unroll
        for (int m=0;m<3;m++)
            out[(i*DIMC+dd)*3+m] = sp[0][dd][m]+sp[1][dd][m]+sp[2][dd][m]+sp[3][dd][m];
    }
}
__global__ __launch_bounds__(256) void k_x2res(const float* __restrict__ x2, const float* __restrict__ r2,
                        float* __restrict__ out){
    int i = blockIdx.x;
    int d = threadIdx.x & 63, jc = threadIdx.x >> 6;
    __shared__ float sp[4][64][5];
    float a[5] = {0.f,0.f,0.f,0.f,0.f};
    #pragma unroll 4
    for (int jj=0;jj<32;jj++){
        int j = jc*32 + jj;
        float o4 = g_out[((i*NN+j)*SSC + 4)*DIMC + d];
        float o2 = g_out[((i*NN+j)*SSC + 2)*DIMC + d];
        const float* xp = &x2[(j*DIMC + d)*5];
        const float* rp = &r2[(i*NN + j)*5];
        #pragma unroll
        for (int m=0;m<5;m++) a[m] += xp[m]*o4 + rp[m]*o2;
    }
    #pragma unroll
    for (int m=0;m<5;m++) sp[jc][d][m] = a[m];
    __syncthreads();
    if (threadIdx.x < 64){
        int dd = threadIdx.x;
        #pragma unroll
        for (int m=0;m<5;m++)
            out[(i*DIMC+dd)*5+m] = sp[0][dd][m]+sp[1][dd][m]+sp[2][dd][m]+sp[3][dd][m];
    }
}

extern "C" void kernel_launch(void* const* d_in, const int* in_sizes, int n_in,
                              void* d_out, int out_size){
    const float* h    = (const float*)d_in[0];
    const float* x1   = (const float*)d_in[1];
    const float* x2   = (const float*)d_in[2];
    const float* t_ij = (const float*)d_in[3];
    const float* r1   = (const float*)d_in[4];
    const float* r2   = (const float*)d_in[5];
    const float* wi   = (const float*)d_in[6];
    const float* wj   = (const float*)d_in[7];
    const float* Wq   = (const float*)d_in[8];
    const float* Wk   = (const float*)d_in[9];
    const float* Wv1  = (const float*)d_in[10];
    const float* bv1  = (const float*)d_in[11];
    const float* Wv2  = (const float*)d_in[12];
    const float* bv2  = (const float*)d_in[13];
    const float* Wp1  = (const float*)d_in[14];
    const float* bp1  = (const float*)d_in[15];
    const float* Wp2  = (const float*)d_in[16];
    const float* bp2  = (const float*)d_in[17];
    const float* We   = (const float*)d_in[18];
    const float* Wc   = (const float*)d_in[19];
    float* out = (float*)d_out;

    // R13 launch order restored.
    k_ln<<<NN, 64>>>(h, wi, wj);
    k_q<<<NN, 256>>>(Wq);
    k_gemm_k64<<<dim3(8,4),  256>>>(1, Wk,  nullptr, DI,   0);
    k_evsum<<<dim3(20, NN), 128, 32768>>>(We, t_ij);
    k_den<<<dim3(NN, SSC), 256>>>();
    k_gemm_k64<<<dim3(16,4), 256>>>(2, Wv1, bv1,     DMLP, 1);
    k_gemm_k64<<<dim3(16,4), 256>>>(3, Wp1, bp1,     DMLP, 1);
    k_mlp2<<<dim3(40,2,2), 128>>>(Wv2, bv2, Wp2, bp2);
    k_sn<<<dim3(8,8,8), 256>>>();
    k_vc<<<dim3(NN,SSC), 256>>>(Wc);
    k_G<<<dim3(NN,SSC), 128>>>(We, Wc);
    k_out<<<dim3(32,8), 256>>>(t_ij);
    k_hres<<<NN, 256>>>(h, out);
    k_x1res<<<NN, 256>>>(x1, r1, out + NN*DIMC);
    k_x2res<<<NN, 256>>>(x2, r2, out + NN*DIMC*4);
}